// round 1
// baseline (speedup 1.0000x reference)
#include <cuda_runtime.h>
#include <math_constants.h>

// Problem constants
#define BB 2
#define SS 2048
#define DD 1024
#define HH 16
#define DKK 64
#define MROWS (BB*SS)   // 4096

// Scratch (allocation-free rule: __device__ globals)
__device__ float g_qh[BB*HH*SS*DKK];   // [B,H,S,DK]
__device__ float g_kh[BB*HH*SS*DKK];
__device__ float g_vh[BB*HH*SS*DKK];
__device__ float g_ao[BB*SS*DD];       // attention output, merged [B,S,D]

// ---------------------------------------------------------------------------
// GEMM: C = X[M,K] @ W[N,K]^T  (M=4096, N=K=1024), 64x64 tile, 4x4 per thread
// SPLIT: scatter output into [B,H,S,DK] head layout
// ---------------------------------------------------------------------------
template<bool SPLIT>
__global__ void __launch_bounds__(256) gemm_xwt(const float* __restrict__ X,
                                                const float* __restrict__ W,
                                                float* __restrict__ C) {
    const int N = DD, K = DD;
    __shared__ float Xs[64][17];
    __shared__ float Ws[64][17];

    int tid = threadIdx.x;
    int tx = tid & 15, ty = tid >> 4;       // 16x16 thread grid
    int row0 = blockIdx.y * 64;
    int col0 = blockIdx.x * 64;
    int lr = tid >> 2;                      // 0..63
    int lc = (tid & 3) * 4;                 // 0,4,8,12

    float acc[4][4];
#pragma unroll
    for (int i = 0; i < 4; i++)
#pragma unroll
        for (int j = 0; j < 4; j++) acc[i][j] = 0.f;

    const float* xp = X + (size_t)(row0 + lr) * K + lc;
    const float* wp = W + (size_t)(col0 + lr) * K + lc;

    for (int k0 = 0; k0 < K; k0 += 16) {
        float4 xv = *(const float4*)(xp + k0);
        float4 wv = *(const float4*)(wp + k0);
        Xs[lr][lc+0] = xv.x; Xs[lr][lc+1] = xv.y; Xs[lr][lc+2] = xv.z; Xs[lr][lc+3] = xv.w;
        Ws[lr][lc+0] = wv.x; Ws[lr][lc+1] = wv.y; Ws[lr][lc+2] = wv.z; Ws[lr][lc+3] = wv.w;
        __syncthreads();

#pragma unroll
        for (int kk = 0; kk < 16; kk++) {
            float a[4], b[4];
#pragma unroll
            for (int i = 0; i < 4; i++) a[i] = Xs[ty*4+i][kk];
#pragma unroll
            for (int j = 0; j < 4; j++) b[j] = Ws[tx*4+j][kk];
#pragma unroll
            for (int i = 0; i < 4; i++)
#pragma unroll
                for (int j = 0; j < 4; j++) acc[i][j] += a[i] * b[j];
        }
        __syncthreads();
    }

#pragma unroll
    for (int i = 0; i < 4; i++) {
        int m = row0 + ty*4 + i;
#pragma unroll
        for (int j = 0; j < 4; j++) {
            int n = col0 + tx*4 + j;
            if (SPLIT) {
                int b_ = m >> 11;           // /S (2048)
                int s_ = m & 2047;
                int h_ = n >> 6;            // /DK (64)
                int dk = n & 63;
                C[(((size_t)(b_*HH + h_)) * SS + s_) * DKK + dk] = acc[i][j];
            } else {
                C[(size_t)m * N + n] = acc[i][j];
            }
        }
    }
}

// ---------------------------------------------------------------------------
// Flash attention: one block per (b*h, q-tile of 64 rows). 256 threads:
// 4 threads per q-row; each owns 16 score cols / 16 output dk cols.
// Causal mask computed analytically (mask input == tril).
// ---------------------------------------------------------------------------
#define LDP 68   // padded row stride (floats); 68*4=272 bytes, 16B aligned

__global__ void __launch_bounds__(256) attn_kernel(const float* __restrict__ qh,
                                                   const float* __restrict__ kh,
                                                   const float* __restrict__ vh,
                                                   float* __restrict__ out) {
    extern __shared__ float sm[];
    float* Qs = sm;                // [64][LDP]
    float* Ks = sm + 64*LDP;
    float* Vs = sm + 2*64*LDP;
    float* Ps = sm + 3*64*LDP;

    int tid = threadIdx.x;
    int r  = tid >> 2;             // q-row within tile, 0..63
    int ql = tid & 3;              // lane group
    int cb = ql * 16;              // column base (scores & output dk)

    int bh = blockIdx.y;           // 0..B*H-1
    int q0 = blockIdx.x * 64;

    const float* qb = qh + (size_t)bh * SS * DKK;
    const float* kb = kh + (size_t)bh * SS * DKK;
    const float* vb = vh + (size_t)bh * SS * DKK;

    // Load Q tile, pre-scaled by 1/sqrt(DK) = 0.125
    {
        int lr = tid >> 2;
        int lc = (tid & 3) * 16;
        const float sc = 0.125f;
#pragma unroll
        for (int t = 0; t < 4; t++) {
            float4 v = *(const float4*)(qb + (size_t)(q0 + lr) * DKK + lc + t*4);
            float* d = &Qs[lr*LDP + lc + t*4];
            d[0] = v.x*sc; d[1] = v.y*sc; d[2] = v.z*sc; d[3] = v.w*sc;
        }
    }

    float m_i = -CUDART_INF_F;
    float l_i = 0.f;
    float o[16];
#pragma unroll
    for (int j = 0; j < 16; j++) o[j] = 0.f;

    int ktiles = (q0 >> 6) + 1;    // causal: only tiles with k0 <= q0

    for (int kt = 0; kt < ktiles; kt++) {
        int k0 = kt * 64;
        __syncthreads();   // previous iter done reading Ks/Vs/Ps
        {
            int lr = tid >> 2;
            int lc = (tid & 3) * 16;
#pragma unroll
            for (int t = 0; t < 4; t++) {
                float4 kv = *(const float4*)(kb + (size_t)(k0 + lr) * DKK + lc + t*4);
                float4 vv = *(const float4*)(vb + (size_t)(k0 + lr) * DKK + lc + t*4);
                *(float4*)&Ks[lr*LDP + lc + t*4] = kv;
                *(float4*)&Vs[lr*LDP + lc + t*4] = vv;
            }
        }
        __syncthreads();

        // scores s[j] = Q[r,:] . K[cb+j,:]
        float s[16];
#pragma unroll
        for (int j = 0; j < 16; j++) s[j] = 0.f;

#pragma unroll
        for (int kc = 0; kc < 64; kc += 16) {
            float qv[16];
#pragma unroll
            for (int t = 0; t < 4; t++) {
                float4 v = *(const float4*)&Qs[r*LDP + kc + t*4];
                qv[t*4+0] = v.x; qv[t*4+1] = v.y; qv[t*4+2] = v.z; qv[t*4+3] = v.w;
            }
#pragma unroll
            for (int j = 0; j < 16; j++) {
                const float* krow = &Ks[(cb + j)*LDP + kc];
#pragma unroll
                for (int t = 0; t < 4; t++) {
                    float4 v = *(const float4*)(krow + t*4);
                    s[j] += qv[t*4+0]*v.x + qv[t*4+1]*v.y + qv[t*4+2]*v.z + qv[t*4+3]*v.w;
                }
            }
        }

        // causal mask (only ever triggers on the diagonal tile)
#pragma unroll
        for (int j = 0; j < 16; j++)
            if (k0 + cb + j > q0 + r) s[j] = -1e30f;

        // online softmax
        float mt = -CUDART_INF_F;
#pragma unroll
        for (int j = 0; j < 16; j++) mt = fmaxf(mt, s[j]);
        mt = fmaxf(mt, __shfl_xor_sync(0xffffffffu, mt, 1));
        mt = fmaxf(mt, __shfl_xor_sync(0xffffffffu, mt, 2));

        float m_new = fmaxf(m_i, mt);
        float alpha = __expf(m_i - m_new);
        float p[16];
        float lsum = 0.f;
#pragma unroll
        for (int j = 0; j < 16; j++) { p[j] = __expf(s[j] - m_new); lsum += p[j]; }
        lsum += __shfl_xor_sync(0xffffffffu, lsum, 1);
        lsum += __shfl_xor_sync(0xffffffffu, lsum, 2);
        l_i = l_i * alpha + lsum;
        m_i = m_new;
#pragma unroll
        for (int j = 0; j < 16; j++) o[j] *= alpha;

        // publish P row chunk
#pragma unroll
        for (int t = 0; t < 4; t++)
            *(float4*)&Ps[r*LDP + cb + t*4] = make_float4(p[t*4+0], p[t*4+1], p[t*4+2], p[t*4+3]);
        __syncthreads();

        // o[j] += sum_kk P[r,kk] * V[kk, cb+j]
#pragma unroll
        for (int kc = 0; kc < 64; kc += 16) {
            float pv[16];
#pragma unroll
            for (int t = 0; t < 4; t++) {
                float4 v = *(const float4*)&Ps[r*LDP + kc + t*4];
                pv[t*4+0] = v.x; pv[t*4+1] = v.y; pv[t*4+2] = v.z; pv[t*4+3] = v.w;
            }
#pragma unroll
            for (int kk = 0; kk < 16; kk++) {
                const float* vrow = &Vs[(kc + kk)*LDP + cb];
                float pk = pv[kk];
#pragma unroll
                for (int t = 0; t < 4; t++) {
                    float4 v = *(const float4*)(vrow + t*4);
                    o[t*4+0] += pk*v.x; o[t*4+1] += pk*v.y; o[t*4+2] += pk*v.z; o[t*4+3] += pk*v.w;
                }
            }
        }
    }

    // epilogue: normalize and write merged [B,S,D]
    float inv = 1.f / l_i;
    int b_ = bh >> 4;              // /H
    int h_ = bh & 15;
    float* op = out + ((size_t)(b_*SS + q0 + r)) * DD + h_ * DKK + cb;
#pragma unroll
    for (int t = 0; t < 4; t++)
        *(float4*)(op + t*4) = make_float4(o[t*4+0]*inv, o[t*4+1]*inv, o[t*4+2]*inv, o[t*4+3]*inv);
}

// ---------------------------------------------------------------------------
extern "C" void kernel_launch(void* const* d_in, const int* in_sizes, int n_in,
                              void* d_out, int out_size) {
    const float* q   = (const float*)d_in[0];
    const float* k   = (const float*)d_in[1];
    const float* v   = (const float*)d_in[2];
    // d_in[3] = mask (tril, computed analytically in the attention kernel)
    const float* W_q = (const float*)d_in[4];
    const float* W_k = (const float*)d_in[5];
    const float* W_v = (const float*)d_in[6];
    const float* W_o = (const float*)d_in[7];
    float* out = (float*)d_out;

    float *qh, *kh, *vh, *ao;
    cudaGetSymbolAddress((void**)&qh, g_qh);
    cudaGetSymbolAddress((void**)&kh, g_kh);
    cudaGetSymbolAddress((void**)&vh, g_vh);
    cudaGetSymbolAddress((void**)&ao, g_ao);

    dim3 ggrid(DD/64, MROWS/64);   // 16 x 64
    gemm_xwt<true><<<ggrid, 256>>>(q, W_q, qh);
    gemm_xwt<true><<<ggrid, 256>>>(k, W_k, kh);
    gemm_xwt<true><<<ggrid, 256>>>(v, W_v, vh);

    size_t attn_smem = (size_t)4 * 64 * LDP * sizeof(float);  // ~69.6 KB
    cudaFuncSetAttribute(attn_kernel, cudaFuncAttributeMaxDynamicSharedMemorySize,
                         (int)attn_smem);
    dim3 agrid(SS/64, BB*HH);      // 32 x 32
    attn_kernel<<<agrid, 256, attn_smem>>>(qh, kh, vh, ao);

    gemm_xwt<false><<<ggrid, 256>>>(ao, W_o, out);
}

// round 4
// speedup vs baseline: 1.1400x; 1.1400x over previous
#include <cuda_runtime.h>
#include <cuda_bf16.h>
#include <math_constants.h>
#include <cstdint>

// Problem constants
#define BB 2
#define SS 2048
#define DD 1024
#define HH 16
#define DKK 64
#define MROWS (BB*SS)   // 4096
#define KTOT 3072       // 3 * 1024 (hi/lo split concatenated K)

// ---------------------------------------------------------------------------
// Scratch (__device__ globals; no runtime allocation allowed)
// ---------------------------------------------------------------------------
__device__ float g_q[MROWS*DD];
__device__ float g_k[MROWS*DD];
__device__ float g_v[MROWS*DD];
__device__ float g_ao[MROWS*DD];
__device__ __nv_bfloat16 g_xp[(size_t)MROWS*KTOT];  // activations [hi,hi,lo]
__device__ __nv_bfloat16 g_wp[(size_t)DD*KTOT];     // weights     [hi,lo,hi]

// ---------------------------------------------------------------------------
// PTX helpers (sm_80-era instructions only — valid on plain sm_103 target)
// ---------------------------------------------------------------------------
__device__ __forceinline__ uint32_t s2u(const void* p){
    uint32_t a;
    asm("{ .reg .u64 t; cvta.to.shared.u64 t, %1; cvt.u32.u64 %0, t; }" : "=r"(a) : "l"(p));
    return a;
}
__device__ __forceinline__ void cpa16(uint32_t dst, const void* src){
    asm volatile("cp.async.cg.shared.global [%0], [%1], 16;" :: "r"(dst), "l"(src));
}
__device__ __forceinline__ void ldsm4(uint32_t* r, uint32_t addr){
    asm volatile("ldmatrix.sync.aligned.m8n8.x4.shared.b16 {%0,%1,%2,%3}, [%4];"
        : "=r"(r[0]), "=r"(r[1]), "=r"(r[2]), "=r"(r[3]) : "r"(addr));
}
__device__ __forceinline__ void mma16816(float* d, const uint32_t* a, const uint32_t* b){
    asm volatile("mma.sync.aligned.m16n8k16.row.col.f32.bf16.bf16.f32 "
        "{%0,%1,%2,%3}, {%4,%5,%6,%7}, {%8,%9}, {%0,%1,%2,%3};"
        : "+f"(d[0]), "+f"(d[1]), "+f"(d[2]), "+f"(d[3])
        : "r"(a[0]), "r"(a[1]), "r"(a[2]), "r"(a[3]), "r"(b[0]), "r"(b[1]));
}

// ---------------------------------------------------------------------------
// hi/lo bf16 conversion.
// XM=true  (activations): segments [hi, hi, lo]
// XM=false (weights):     segments [hi, lo, hi]
// ---------------------------------------------------------------------------
template<bool XM>
__global__ void __launch_bounds__(256) convhl(const float* __restrict__ X,
                                              __nv_bfloat16* __restrict__ O){
    int idx = blockIdx.x * 256 + threadIdx.x;
    float4 v = ((const float4*)X)[idx];
    int m = idx >> 8;
    int j = (idx & 255) * 4;
    size_t o = (size_t)m * KTOT + j;

    float f[4] = {v.x, v.y, v.z, v.w};
    __nv_bfloat16 hi[4], lo[4];
#pragma unroll
    for (int t = 0; t < 4; t++){
        hi[t] = __float2bfloat16(f[t]);
        lo[t] = __float2bfloat16(f[t] - __bfloat162float(hi[t]));
    }
    __nv_bfloat162 h01 = __halves2bfloat162(hi[0], hi[1]);
    __nv_bfloat162 h23 = __halves2bfloat162(hi[2], hi[3]);
    __nv_bfloat162 l01 = __halves2bfloat162(lo[0], lo[1]);
    __nv_bfloat162 l23 = __halves2bfloat162(lo[2], lo[3]);

    __nv_bfloat162* p0 = (__nv_bfloat162*)(O + o);
    __nv_bfloat162* p1 = (__nv_bfloat162*)(O + o + 1024);
    __nv_bfloat162* p2 = (__nv_bfloat162*)(O + o + 2048);
    p0[0] = h01; p0[1] = h23;
    if (XM){ p1[0] = h01; p1[1] = h23; p2[0] = l01; p2[1] = l23; }
    else   { p1[0] = l01; p1[1] = l23; p2[0] = h01; p2[1] = h23; }
}

// ---------------------------------------------------------------------------
// mma.sync bf16 GEMM: C[4096,1024] = A'[4096,3072] @ B'[1024,3072]^T
// CTA tile 128x128, 8 warps (each 32x64), BK=32, 3-stage cp.async pipeline.
// smem rows padded to 40 elems (80B) -> conflict-free 8-row ldmatrix.
// ---------------------------------------------------------------------------
#define BKK 32
#define TSTRIDE 40                       // elems per smem row
#define TILEB  (128*TSTRIDE*2)           // 10240 B per tile
#define STAGEB (2*TILEB)                 // A+B per stage
#define GSMEM  (3*STAGEB)                // 61440 B
#define NKT    (KTOT/BKK)                // 96

__global__ void __launch_bounds__(256, 1) gemm_mma(const __nv_bfloat16* __restrict__ Ag,
                                                   const __nv_bfloat16* __restrict__ Bg,
                                                   float* __restrict__ C){
    extern __shared__ char smem[];
    uint32_t sb = s2u(smem);
    int tid = threadIdx.x, lane = tid & 31, wid = tid >> 5;
    int wm = wid & 3, wn = wid >> 1 & 0x4 ? 0 : wid >> 2;  // placeholder fixed below
    wn = wid >> 2;                                          // 0..1

    const char* Ab = (const char*)Ag + (size_t)(blockIdx.y * 128) * (KTOT * 2);
    const char* Bb = (const char*)Bg + (size_t)(blockIdx.x * 128) * (KTOT * 2);

    // per-thread ldmatrix byte offsets within a tile
    uint32_t offA[2], offB[4];
#pragma unroll
    for (int mt = 0; mt < 2; mt++)
        offA[mt] = ((wm*32 + mt*16 + (lane & 15)) * TSTRIDE + ((lane >> 4) * 8)) * 2;
#pragma unroll
    for (int q = 0; q < 4; q++)
        offB[q] = ((wn*64 + q*16 + ((lane >> 4) & 1) * 8 + (lane & 7)) * TSTRIDE
                   + (((lane >> 3) & 1) * 8)) * 2;

    int lr0 = tid >> 2;            // row 0..63 (i=0), +64 (i=1)
    int lc4 = (tid & 3) * 16;      // byte chunk within 64B row data

    float acc[2][8][4];
#pragma unroll
    for (int a = 0; a < 2; a++)
#pragma unroll
        for (int b = 0; b < 8; b++)
#pragma unroll
            for (int c = 0; c < 4; c++) acc[a][b][c] = 0.f;

#define LOADSTAGE(kt, s) do {                                                   \
        uint32_t a0_ = sb + (s) * STAGEB;                                       \
        uint32_t b0_ = a0_ + TILEB;                                             \
        size_t gk_ = (size_t)(kt) * 64;                                         \
        _Pragma("unroll")                                                       \
        for (int i_ = 0; i_ < 2; i_++){                                         \
            int r_ = lr0 + i_ * 64;                                             \
            cpa16(a0_ + r_ * 80 + lc4, Ab + (size_t)r_ * (KTOT*2) + gk_ + lc4); \
            cpa16(b0_ + r_ * 80 + lc4, Bb + (size_t)r_ * (KTOT*2) + gk_ + lc4); \
        }                                                                       \
        asm volatile("cp.async.commit_group;" ::: "memory");                    \
    } while (0)

    LOADSTAGE(0, 0);
    LOADSTAGE(1, 1);

    for (int kt = 0; kt < NKT; kt++){
        if (kt == NKT - 1) asm volatile("cp.async.wait_group 0;" ::: "memory");
        else               asm volatile("cp.async.wait_group 1;" ::: "memory");
        __syncthreads();
        if (kt + 2 < NKT){ int s2 = (kt + 2) % 3; LOADSTAGE(kt + 2, s2); }

        uint32_t a0 = sb + (kt % 3) * STAGEB;
        uint32_t b0 = a0 + TILEB;
#pragma unroll
        for (int kk = 0; kk < 2; kk++){
            uint32_t a[2][4], b[4][4];
            ldsm4(a[0], a0 + offA[0] + kk * 32);
            ldsm4(a[1], a0 + offA[1] + kk * 32);
#pragma unroll
            for (int q = 0; q < 4; q++) ldsm4(b[q], b0 + offB[q] + kk * 32);
#pragma unroll
            for (int mt = 0; mt < 2; mt++)
#pragma unroll
                for (int nt = 0; nt < 8; nt++)
                    mma16816(acc[mt][nt], a[mt], &b[nt >> 1][(nt & 1) * 2]);
        }
    }

    // epilogue
    int m0 = blockIdx.y * 128 + wm * 32 + (lane >> 2);
    int n0 = blockIdx.x * 128 + wn * 64 + (lane & 3) * 2;
#pragma unroll
    for (int mt = 0; mt < 2; mt++){
#pragma unroll
        for (int nt = 0; nt < 8; nt++){
            float* p = C + (size_t)(m0 + mt * 16) * DD + n0 + nt * 8;
            *(float2*)p = make_float2(acc[mt][nt][0], acc[mt][nt][1]);
            *(float2*)(p + 8 * DD) = make_float2(acc[mt][nt][2], acc[mt][nt][3]);
        }
    }
}

// ---------------------------------------------------------------------------
// Flash attention (SIMT; reads merged [B*S, D] layout)
// ---------------------------------------------------------------------------
#define LDP 68

__global__ void __launch_bounds__(256) attn_kernel(const float* __restrict__ qh,
                                                   const float* __restrict__ kh,
                                                   const float* __restrict__ vh,
                                                   float* __restrict__ out) {
    extern __shared__ float sm[];
    float* Qs = sm;
    float* Ks = sm + 64*LDP;
    float* Vs = sm + 2*64*LDP;
    float* Ps = sm + 3*64*LDP;

    int tid = threadIdx.x;
    int r  = tid >> 2;
    int ql = tid & 3;
    int cb = ql * 16;

    int bh = blockIdx.y;
    int q0 = blockIdx.x * 64;
    int b_ = bh >> 4;
    int h_ = bh & 15;

    const float* qb = qh + (size_t)(b_*SS)*DD + h_*DKK;
    const float* kb = kh + (size_t)(b_*SS)*DD + h_*DKK;
    const float* vb = vh + (size_t)(b_*SS)*DD + h_*DKK;

    {
        int lr = tid >> 2;
        int lc = (tid & 3) * 16;
        const float sc = 0.125f;
#pragma unroll
        for (int t = 0; t < 4; t++) {
            float4 v = *(const float4*)(qb + (size_t)(q0 + lr) * DD + lc + t*4);
            float* d = &Qs[lr*LDP + lc + t*4];
            d[0] = v.x*sc; d[1] = v.y*sc; d[2] = v.z*sc; d[3] = v.w*sc;
        }
    }

    float m_i = -CUDART_INF_F;
    float l_i = 0.f;
    float o[16];
#pragma unroll
    for (int j = 0; j < 16; j++) o[j] = 0.f;

    int ktiles = (q0 >> 6) + 1;

    for (int kt = 0; kt < ktiles; kt++) {
        int k0 = kt * 64;
        __syncthreads();
        {
            int lr = tid >> 2;
            int lc = (tid & 3) * 16;
#pragma unroll
            for (int t = 0; t < 4; t++) {
                float4 kv = *(const float4*)(kb + (size_t)(k0 + lr) * DD + lc + t*4);
                float4 vv = *(const float4*)(vb + (size_t)(k0 + lr) * DD + lc + t*4);
                *(float4*)&Ks[lr*LDP + lc + t*4] = kv;
                *(float4*)&Vs[lr*LDP + lc + t*4] = vv;
            }
        }
        __syncthreads();

        float s[16];
#pragma unroll
        for (int j = 0; j < 16; j++) s[j] = 0.f;

#pragma unroll
        for (int kc = 0; kc < 64; kc += 16) {
            float qv[16];
#pragma unroll
            for (int t = 0; t < 4; t++) {
                float4 v = *(const float4*)&Qs[r*LDP + kc + t*4];
                qv[t*4+0] = v.x; qv[t*4+1] = v.y; qv[t*4+2] = v.z; qv[t*4+3] = v.w;
            }
#pragma unroll
            for (int j = 0; j < 16; j++) {
                const float* krow = &Ks[(cb + j)*LDP + kc];
#pragma unroll
                for (int t = 0; t < 4; t++) {
                    float4 v = *(const float4*)(krow + t*4);
                    s[j] += qv[t*4+0]*v.x + qv[t*4+1]*v.y + qv[t*4+2]*v.z + qv[t*4+3]*v.w;
                }
            }
        }

#pragma unroll
        for (int j = 0; j < 16; j++)
            if (k0 + cb + j > q0 + r) s[j] = -1e30f;

        float mt = -CUDART_INF_F;
#pragma unroll
        for (int j = 0; j < 16; j++) mt = fmaxf(mt, s[j]);
        mt = fmaxf(mt, __shfl_xor_sync(0xffffffffu, mt, 1));
        mt = fmaxf(mt, __shfl_xor_sync(0xffffffffu, mt, 2));

        float m_new = fmaxf(m_i, mt);
        float alpha = __expf(m_i - m_new);
        float p[16];
        float lsum = 0.f;
#pragma unroll
        for (int j = 0; j < 16; j++) { p[j] = __expf(s[j] - m_new); lsum += p[j]; }
        lsum += __shfl_xor_sync(0xffffffffu, lsum, 1);
        lsum += __shfl_xor_sync(0xffffffffu, lsum, 2);
        l_i = l_i * alpha + lsum;
        m_i = m_new;
#pragma unroll
        for (int j = 0; j < 16; j++) o[j] *= alpha;

#pragma unroll
        for (int t = 0; t < 4; t++)
            *(float4*)&Ps[r*LDP + cb + t*4] = make_float4(p[t*4+0], p[t*4+1], p[t*4+2], p[t*4+3]);
        __syncthreads();

#pragma unroll
        for (int kc = 0; kc < 64; kc += 16) {
            float pv[16];
#pragma unroll
            for (int t = 0; t < 4; t++) {
                float4 v = *(const float4*)&Ps[r*LDP + kc + t*4];
                pv[t*4+0] = v.x; pv[t*4+1] = v.y; pv[t*4+2] = v.z; pv[t*4+3] = v.w;
            }
#pragma unroll
            for (int kk = 0; kk < 16; kk++) {
                const float* vrow = &Vs[(kc + kk)*LDP + cb];
                float pk = pv[kk];
#pragma unroll
                for (int t = 0; t < 4; t++) {
                    float4 v = *(const float4*)(vrow + t*4);
                    o[t*4+0] += pk*v.x; o[t*4+1] += pk*v.y; o[t*4+2] += pk*v.z; o[t*4+3] += pk*v.w;
                }
            }
        }
    }

    float inv = 1.f / l_i;
    float* op = out + ((size_t)(b_*SS + q0 + r)) * DD + h_ * DKK + cb;
#pragma unroll
    for (int t = 0; t < 4; t++)
        *(float4*)(op + t*4) = make_float4(o[t*4+0]*inv, o[t*4+1]*inv, o[t*4+2]*inv, o[t*4+3]*inv);
}

// ---------------------------------------------------------------------------
extern "C" void kernel_launch(void* const* d_in, const int* in_sizes, int n_in,
                              void* d_out, int out_size) {
    const float* q   = (const float*)d_in[0];
    const float* k   = (const float*)d_in[1];
    const float* v   = (const float*)d_in[2];
    // d_in[3] = mask (tril; computed analytically)
    const float* W_q = (const float*)d_in[4];
    const float* W_k = (const float*)d_in[5];
    const float* W_v = (const float*)d_in[6];
    const float* W_o = (const float*)d_in[7];
    float* out = (float*)d_out;

    float *qp, *kp, *vp, *ao;
    __nv_bfloat16 *xp, *wp;
    cudaGetSymbolAddress((void**)&qp, g_q);
    cudaGetSymbolAddress((void**)&kp, g_k);
    cudaGetSymbolAddress((void**)&vp, g_v);
    cudaGetSymbolAddress((void**)&ao, g_ao);
    cudaGetSymbolAddress((void**)&xp, g_xp);
    cudaGetSymbolAddress((void**)&wp, g_wp);

    cudaFuncSetAttribute(gemm_mma, cudaFuncAttributeMaxDynamicSharedMemorySize, GSMEM);

    const int XBLKS = MROWS * DD / 4 / 256;   // 4096
    const int WBLKS = DD * DD / 4 / 256;      // 1024
    dim3 ggrid(DD / 128, MROWS / 128);        // (8, 32)

    convhl<false><<<WBLKS, 256>>>(W_q, wp);
    convhl<true ><<<XBLKS, 256>>>(q, xp);
    gemm_mma<<<ggrid, 256, GSMEM>>>(xp, wp, qp);

    convhl<false><<<WBLKS, 256>>>(W_k, wp);
    convhl<true ><<<XBLKS, 256>>>(k, xp);
    gemm_mma<<<ggrid, 256, GSMEM>>>(xp, wp, kp);

    convhl<false><<<WBLKS, 256>>>(W_v, wp);
    convhl<true ><<<XBLKS, 256>>>(v, xp);
    gemm_mma<<<ggrid, 256, GSMEM>>>(xp, wp, vp);

    size_t attn_smem = (size_t)4 * 64 * LDP * sizeof(float);
    cudaFuncSetAttribute(attn_kernel, cudaFuncAttributeMaxDynamicSharedMemorySize,
                         (int)attn_smem);
    dim3 agrid(SS/64, BB*HH);
    attn_kernel<<<agrid, 256, attn_smem>>>(qp, kp, vp, ao);

    convhl<false><<<WBLKS, 256>>>(W_o, wp);
    convhl<true ><<<XBLKS, 256>>>(ao, xp);
    gemm_mma<<<ggrid, 256, GSMEM>>>(xp, wp, out);
}

// round 6
// speedup vs baseline: 4.2029x; 3.6867x over previous
#include <cuda_runtime.h>
#include <cuda_bf16.h>
#include <math_constants.h>
#include <cstdint>

// Problem constants
#define BB 2
#define SS 2048
#define DD 1024
#define HH 16
#define DKK 64
#define MROWS (BB*SS)   // 4096
#define KTOT 3072       // 3 * 1024 (hi/lo split concatenated K)

// ---------------------------------------------------------------------------
// Scratch (__device__ globals; no runtime allocation allowed)
// ---------------------------------------------------------------------------
__device__ float g_q[MROWS*DD];
__device__ float g_k[MROWS*DD];
__device__ float g_v[MROWS*DD];
__device__ float g_ao[MROWS*DD];
__device__ __nv_bfloat16 g_xp[(size_t)MROWS*KTOT];  // activations [hi,hi,lo]
__device__ __nv_bfloat16 g_wp[(size_t)DD*KTOT];     // weights     [hi,lo,hi]

// ---------------------------------------------------------------------------
// PTX helpers (sm_80-era instructions only — valid on plain sm_103 target)
// ---------------------------------------------------------------------------
__device__ __forceinline__ uint32_t s2u(const void* p){
    uint32_t a;
    asm("{ .reg .u64 t; cvta.to.shared.u64 t, %1; cvt.u32.u64 %0, t; }" : "=r"(a) : "l"(p));
    return a;
}
__device__ __forceinline__ void cpa16(uint32_t dst, const void* src){
    asm volatile("cp.async.cg.shared.global [%0], [%1], 16;" :: "r"(dst), "l"(src));
}
__device__ __forceinline__ void ldsm4(uint32_t* r, uint32_t addr){
    asm volatile("ldmatrix.sync.aligned.m8n8.x4.shared.b16 {%0,%1,%2,%3}, [%4];"
        : "=r"(r[0]), "=r"(r[1]), "=r"(r[2]), "=r"(r[3]) : "r"(addr));
}
__device__ __forceinline__ void mma16816(float* d, const uint32_t* a, const uint32_t* b){
    asm volatile("mma.sync.aligned.m16n8k16.row.col.f32.bf16.bf16.f32 "
        "{%0,%1,%2,%3}, {%4,%5,%6,%7}, {%8,%9}, {%0,%1,%2,%3};"
        : "+f"(d[0]), "+f"(d[1]), "+f"(d[2]), "+f"(d[3])
        : "r"(a[0]), "r"(a[1]), "r"(a[2]), "r"(a[3]), "r"(b[0]), "r"(b[1]));
}

// ---------------------------------------------------------------------------
// hi/lo bf16 conversion.
// XM=true  (activations): segments [hi, hi, lo]
// XM=false (weights):     segments [hi, lo, hi]
// ---------------------------------------------------------------------------
template<bool XM>
__global__ void __launch_bounds__(256) convhl(const float* __restrict__ X,
                                              __nv_bfloat16* __restrict__ O){
    int idx = blockIdx.x * 256 + threadIdx.x;
    float4 v = ((const float4*)X)[idx];
    int m = idx >> 8;
    int j = (idx & 255) * 4;
    size_t o = (size_t)m * KTOT + j;

    float f[4] = {v.x, v.y, v.z, v.w};
    __nv_bfloat16 hi[4], lo[4];
#pragma unroll
    for (int t = 0; t < 4; t++){
        hi[t] = __float2bfloat16(f[t]);
        lo[t] = __float2bfloat16(f[t] - __bfloat162float(hi[t]));
    }
    __nv_bfloat162 h01 = __halves2bfloat162(hi[0], hi[1]);
    __nv_bfloat162 h23 = __halves2bfloat162(hi[2], hi[3]);
    __nv_bfloat162 l01 = __halves2bfloat162(lo[0], lo[1]);
    __nv_bfloat162 l23 = __halves2bfloat162(lo[2], lo[3]);

    __nv_bfloat162* p0 = (__nv_bfloat162*)(O + o);
    __nv_bfloat162* p1 = (__nv_bfloat162*)(O + o + 1024);
    __nv_bfloat162* p2 = (__nv_bfloat162*)(O + o + 2048);
    p0[0] = h01; p0[1] = h23;
    if (XM){ p1[0] = h01; p1[1] = h23; p2[0] = l01; p2[1] = l23; }
    else   { p1[0] = l01; p1[1] = l23; p2[0] = h01; p2[1] = h23; }
}

// ---------------------------------------------------------------------------
// mma.sync bf16 GEMM: C[4096,1024] = A'[4096,3072] @ B'[1024,3072]^T
// CTA tile 128x128, 8 warps (each 32x64), BK=32, 3-stage cp.async pipeline.
// ---------------------------------------------------------------------------
#define BKK 32
#define TSTRIDE 40
#define TILEB  (128*TSTRIDE*2)
#define STAGEB (2*TILEB)
#define GSMEM  (3*STAGEB)
#define NKT    (KTOT/BKK)                // 96

__global__ void __launch_bounds__(256, 1) gemm_mma(const __nv_bfloat16* __restrict__ Ag,
                                                   const __nv_bfloat16* __restrict__ Bg,
                                                   float* __restrict__ C){
    extern __shared__ char smem[];
    uint32_t sb = s2u(smem);
    int tid = threadIdx.x, lane = tid & 31, wid = tid >> 5;
    int wm = wid & 3;
    int wn = wid >> 2;

    const char* Ab = (const char*)Ag + (size_t)(blockIdx.y * 128) * (KTOT * 2);
    const char* Bb = (const char*)Bg + (size_t)(blockIdx.x * 128) * (KTOT * 2);

    uint32_t offA[2], offB[4];
#pragma unroll
    for (int mt = 0; mt < 2; mt++)
        offA[mt] = ((wm*32 + mt*16 + (lane & 15)) * TSTRIDE + ((lane >> 4) * 8)) * 2;
#pragma unroll
    for (int q = 0; q < 4; q++)
        offB[q] = ((wn*64 + q*16 + ((lane >> 4) & 1) * 8 + (lane & 7)) * TSTRIDE
                   + (((lane >> 3) & 1) * 8)) * 2;

    int lr0 = tid >> 2;
    int lc4 = (tid & 3) * 16;

    float acc[2][8][4];
#pragma unroll
    for (int a = 0; a < 2; a++)
#pragma unroll
        for (int b = 0; b < 8; b++)
#pragma unroll
            for (int c = 0; c < 4; c++) acc[a][b][c] = 0.f;

#define LOADSTAGE(kt, s) do {                                                   \
        uint32_t a0_ = sb + (s) * STAGEB;                                       \
        uint32_t b0_ = a0_ + TILEB;                                             \
        size_t gk_ = (size_t)(kt) * 64;                                         \
        _Pragma("unroll")                                                       \
        for (int i_ = 0; i_ < 2; i_++){                                         \
            int r_ = lr0 + i_ * 64;                                             \
            cpa16(a0_ + r_ * 80 + lc4, Ab + (size_t)r_ * (KTOT*2) + gk_ + lc4); \
            cpa16(b0_ + r_ * 80 + lc4, Bb + (size_t)r_ * (KTOT*2) + gk_ + lc4); \
        }                                                                       \
        asm volatile("cp.async.commit_group;" ::: "memory");                    \
    } while (0)

    LOADSTAGE(0, 0);
    LOADSTAGE(1, 1);

    for (int kt = 0; kt < NKT; kt++){
        if (kt == NKT - 1) asm volatile("cp.async.wait_group 0;" ::: "memory");
        else               asm volatile("cp.async.wait_group 1;" ::: "memory");
        __syncthreads();
        if (kt + 2 < NKT){ int s2 = (kt + 2) % 3; LOADSTAGE(kt + 2, s2); }

        uint32_t a0 = sb + (kt % 3) * STAGEB;
        uint32_t b0 = a0 + TILEB;
#pragma unroll
        for (int kk = 0; kk < 2; kk++){
            uint32_t a[2][4], b[4][4];
            ldsm4(a[0], a0 + offA[0] + kk * 32);
            ldsm4(a[1], a0 + offA[1] + kk * 32);
#pragma unroll
            for (int q = 0; q < 4; q++) ldsm4(b[q], b0 + offB[q] + kk * 32);
#pragma unroll
            for (int mt = 0; mt < 2; mt++)
#pragma unroll
                for (int nt = 0; nt < 8; nt++)
                    mma16816(acc[mt][nt], a[mt], &b[nt >> 1][(nt & 1) * 2]);
        }
    }

    int m0 = blockIdx.y * 128 + wm * 32 + (lane >> 2);
    int n0 = blockIdx.x * 128 + wn * 64 + (lane & 3) * 2;
#pragma unroll
    for (int mt = 0; mt < 2; mt++){
#pragma unroll
        for (int nt = 0; nt < 8; nt++){
            float* p = C + (size_t)(m0 + mt * 16) * DD + n0 + nt * 8;
            *(float2*)p = make_float2(acc[mt][nt][0], acc[mt][nt][1]);
            *(float2*)(p + 8 * DD) = make_float2(acc[mt][nt][2], acc[mt][nt][3]);
        }
    }
}

// ---------------------------------------------------------------------------
// Flash attention, register-tiled (4x4 per thread) to fix LDS-bound profile.
// Thread grid 16x16; thread = 4 q-rows x (4 k-cols | 4 dk-cols).
// smem: Qt[dk][row] and Kt[dk][col] transposed (conflict-free float4 reads),
// Vs[kc][dk] natural, Ps[row][kc].
// ---------------------------------------------------------------------------
#define APAD 68

__global__ void __launch_bounds__(256) attn_kernel(const float* __restrict__ qh,
                                                   const float* __restrict__ kh,
                                                   const float* __restrict__ vh,
                                                   float* __restrict__ out) {
    extern __shared__ float sm[];
    float* Qt = sm;                 // [64][APAD] : Qt[dk*APAD + row]
    float* Kt = sm + 64*APAD;       // [64][APAD] : Kt[dk*APAD + col]
    float* Vs = sm + 2*64*APAD;     // [64][APAD] : Vs[kc*APAD + dk]
    float* Ps = sm + 3*64*APAD;     // [64][APAD] : Ps[row*APAD + kc]

    int tid = threadIdx.x;
    int tx = tid & 15, ty = tid >> 4;
    int bh = blockIdx.y;
    int q0 = blockIdx.x * 64;
    int b_ = bh >> 4;
    int h_ = bh & 15;

    const float* qb = qh + (size_t)(b_*SS)*DD + h_*DKK;
    const float* kb = kh + (size_t)(b_*SS)*DD + h_*DKK;
    const float* vb = vh + (size_t)(b_*SS)*DD + h_*DKK;

    // Load Q tile transposed, pre-scaled by 1/sqrt(DK)
    {
        int r = tid >> 2;
        int c0 = (tid & 3) * 16;
        const float sc = 0.125f;
#pragma unroll
        for (int t = 0; t < 4; t++) {
            float4 v = *(const float4*)(qb + (size_t)(q0 + r) * DD + c0 + t*4);
            Qt[(c0 + t*4 + 0)*APAD + r] = v.x*sc;
            Qt[(c0 + t*4 + 1)*APAD + r] = v.y*sc;
            Qt[(c0 + t*4 + 2)*APAD + r] = v.z*sc;
            Qt[(c0 + t*4 + 3)*APAD + r] = v.w*sc;
        }
    }

    float m_i[4], l_i[4], o[4][4];
#pragma unroll
    for (int i = 0; i < 4; i++){
        m_i[i] = -CUDART_INF_F; l_i[i] = 0.f;
#pragma unroll
        for (int j = 0; j < 4; j++) o[i][j] = 0.f;
    }

    int ktiles = (q0 >> 6) + 1;

    for (int kt = 0; kt < ktiles; kt++) {
        int k0 = kt * 64;
        __syncthreads();   // previous iteration done with Kt/Vs/Ps
        {
            int r = tid >> 2;
            int c0 = (tid & 3) * 16;
#pragma unroll
            for (int t = 0; t < 4; t++) {
                float4 kv = *(const float4*)(kb + (size_t)(k0 + r) * DD + c0 + t*4);
                Kt[(c0 + t*4 + 0)*APAD + r] = kv.x;
                Kt[(c0 + t*4 + 1)*APAD + r] = kv.y;
                Kt[(c0 + t*4 + 2)*APAD + r] = kv.z;
                Kt[(c0 + t*4 + 3)*APAD + r] = kv.w;
                float4 vv = *(const float4*)(vb + (size_t)(k0 + r) * DD + c0 + t*4);
                *(float4*)&Vs[r*APAD + c0 + t*4] = vv;
            }
        }
        __syncthreads();

        // scores: s[i][j] = sum_dk Qt[dk][4ty+i] * Kt[dk][4tx+j]
        float s[4][4];
#pragma unroll
        for (int i = 0; i < 4; i++)
#pragma unroll
            for (int j = 0; j < 4; j++) s[i][j] = 0.f;

#pragma unroll 8
        for (int dk = 0; dk < 64; dk++){
            float4 a = *(const float4*)&Qt[dk*APAD + 4*ty];
            float4 b = *(const float4*)&Kt[dk*APAD + 4*tx];
            float av[4] = {a.x, a.y, a.z, a.w};
            float bv[4] = {b.x, b.y, b.z, b.w};
#pragma unroll
            for (int i = 0; i < 4; i++)
#pragma unroll
                for (int j = 0; j < 4; j++) s[i][j] += av[i]*bv[j];
        }

        // causal mask: only the diagonal tile can mask
        if (k0 == q0){
#pragma unroll
            for (int i = 0; i < 4; i++)
#pragma unroll
                for (int j = 0; j < 4; j++)
                    if (4*tx + j > 4*ty + i) s[i][j] = -1e30f;
        }

        // online softmax per row i (reduction across tx = lanes xor 1,2,4,8)
#pragma unroll
        for (int i = 0; i < 4; i++){
            float mt = fmaxf(fmaxf(s[i][0], s[i][1]), fmaxf(s[i][2], s[i][3]));
            mt = fmaxf(mt, __shfl_xor_sync(0xffffffffu, mt, 1));
            mt = fmaxf(mt, __shfl_xor_sync(0xffffffffu, mt, 2));
            mt = fmaxf(mt, __shfl_xor_sync(0xffffffffu, mt, 4));
            mt = fmaxf(mt, __shfl_xor_sync(0xffffffffu, mt, 8));
            float m_new = fmaxf(m_i[i], mt);
            float alpha = __expf(m_i[i] - m_new);
            float p[4], lsum = 0.f;
#pragma unroll
            for (int j = 0; j < 4; j++){ p[j] = __expf(s[i][j] - m_new); lsum += p[j]; }
            lsum += __shfl_xor_sync(0xffffffffu, lsum, 1);
            lsum += __shfl_xor_sync(0xffffffffu, lsum, 2);
            lsum += __shfl_xor_sync(0xffffffffu, lsum, 4);
            lsum += __shfl_xor_sync(0xffffffffu, lsum, 8);
            l_i[i] = l_i[i] * alpha + lsum;
            m_i[i] = m_new;
#pragma unroll
            for (int j = 0; j < 4; j++) o[i][j] *= alpha;
            *(float4*)&Ps[(4*ty + i)*APAD + 4*tx] = make_float4(p[0], p[1], p[2], p[3]);
        }
        __syncthreads();

        // PV: o[i][j] += sum_kc Ps[4ty+i][kc] * Vs[kc][4tx+j]
#pragma unroll 4
        for (int kc = 0; kc < 64; kc += 4){
            float4 p4[4];
#pragma unroll
            for (int i = 0; i < 4; i++)
                p4[i] = *(const float4*)&Ps[(4*ty + i)*APAD + kc];
#pragma unroll
            for (int u = 0; u < 4; u++){
                float4 v = *(const float4*)&Vs[(kc + u)*APAD + 4*tx];
                float vv[4] = {v.x, v.y, v.z, v.w};
                float pu[4] = { (&p4[0].x)[u], (&p4[1].x)[u], (&p4[2].x)[u], (&p4[3].x)[u] };
#pragma unroll
                for (int i = 0; i < 4; i++)
#pragma unroll
                    for (int j = 0; j < 4; j++) o[i][j] += pu[i]*vv[j];
            }
        }
    }

    // epilogue: normalize, write merged [B,S,D]
#pragma unroll
    for (int i = 0; i < 4; i++){
        float inv = 1.f / l_i[i];
        int row = q0 + 4*ty + i;
        float* op = out + ((size_t)(b_*SS + row)) * DD + h_ * DKK + 4*tx;
        *(float4*)op = make_float4(o[i][0]*inv, o[i][1]*inv, o[i][2]*inv, o[i][3]*inv);
    }
}

// ---------------------------------------------------------------------------
extern "C" void kernel_launch(void* const* d_in, const int* in_sizes, int n_in,
                              void* d_out, int out_size) {
    const float* q   = (const float*)d_in[0];
    const float* k   = (const float*)d_in[1];
    const float* v   = (const float*)d_in[2];
    // d_in[3] = mask (tril; computed analytically)
    const float* W_q = (const float*)d_in[4];
    const float* W_k = (const float*)d_in[5];
    const float* W_v = (const float*)d_in[6];
    const float* W_o = (const float*)d_in[7];
    float* out = (float*)d_out;

    float *qp, *kp, *vp, *ao;
    __nv_bfloat16 *xp, *wp;
    cudaGetSymbolAddress((void**)&qp, g_q);
    cudaGetSymbolAddress((void**)&kp, g_k);
    cudaGetSymbolAddress((void**)&vp, g_v);
    cudaGetSymbolAddress((void**)&ao, g_ao);
    cudaGetSymbolAddress((void**)&xp, g_xp);
    cudaGetSymbolAddress((void**)&wp, g_wp);

    cudaFuncSetAttribute(gemm_mma, cudaFuncAttributeMaxDynamicSharedMemorySize, GSMEM);

    const int XBLKS = MROWS * DD / 4 / 256;   // 4096
    const int WBLKS = DD * DD / 4 / 256;      // 1024
    dim3 ggrid(DD / 128, MROWS / 128);        // (8, 32)

    convhl<false><<<WBLKS, 256>>>(W_q, wp);
    convhl<true ><<<XBLKS, 256>>>(q, xp);
    gemm_mma<<<ggrid, 256, GSMEM>>>(xp, wp, qp);

    convhl<false><<<WBLKS, 256>>>(W_k, wp);
    convhl<true ><<<XBLKS, 256>>>(k, xp);
    gemm_mma<<<ggrid, 256, GSMEM>>>(xp, wp, kp);

    convhl<false><<<WBLKS, 256>>>(W_v, wp);
    convhl<true ><<<XBLKS, 256>>>(v, xp);
    gemm_mma<<<ggrid, 256, GSMEM>>>(xp, wp, vp);

    size_t attn_smem = (size_t)4 * 64 * APAD * sizeof(float);
    cudaFuncSetAttribute(attn_kernel, cudaFuncAttributeMaxDynamicSharedMemorySize,
                         (int)attn_smem);
    dim3 agrid(SS/64, BB*HH);
    attn_kernel<<<agrid, 256, attn_smem>>>(qp, kp, vp, ao);

    convhl<false><<<WBLKS, 256>>>(W_o, wp);
    convhl<true ><<<XBLKS, 256>>>(ao, xp);
    gemm_mma<<<ggrid, 256, GSMEM>>>(xp, wp, out);
}